// round 10
// baseline (speedup 1.0000x reference)
#include <cuda_runtime.h>
#include <cuda_bf16.h>

// Downsampler: (16,8,1024,1024) fp32, 4x4 Gaussian kernel, stride 4, VALID.
// Output (16,8,256,256) fp32. Non-overlapping windows -> pure streaming.
// R10 (= R8 retry #2, unchanged): R7 + weights staged into __constant__
// memory via async D2D copy (graph-capturable). Per-thread LDG count
// 20 -> 4, freeing the LSU/L1 path for the bulk loads. Single-change vs R7.

#define N_  16
#define C_  8
#define H_  1024
#define W_  1024
#define F_  4
#define HO_ (H_ / F_)   // 256
#define WO_ (W_ / F_)   // 256

__constant__ float c_kw[16];

__global__ __launch_bounds__(256) void Downsampler_24421184045082_kernel(
    const float* __restrict__ x,
    float* __restrict__ out,
    int total)
{
    int o = blockIdx.x * blockDim.x + threadIdx.x;
    if (o >= total) return;

    // Decompose output index: o = ((nc * HO) + oh) * WO + ow
    int ow = o & (WO_ - 1);            // 256 = 2^8
    int oh = (o >> 8) & (HO_ - 1);
    int nc = o >> 16;

    // Base of this thread's 4x4 patch, viewed as float4 rows.
    const float4* x4 = reinterpret_cast<const float4*>(x)
                     + (size_t)nc * (H_ * (W_ / 4))
                     + (size_t)(oh * F_) * (W_ / 4)
                     + ow;

    // 4 independent row loads, evict-first streaming policy (single-use data).
    float4 r0 = __ldcs(x4 + 0 * (W_ / 4));
    float4 r1 = __ldcs(x4 + 1 * (W_ / 4));
    float4 r2 = __ldcs(x4 + 2 * (W_ / 4));
    float4 r3 = __ldcs(x4 + 3 * (W_ / 4));

    // Weights from constant bank (uniform path, no LSU/L1 traffic).
    float acc;
    acc  = c_kw[0]  * r0.x + c_kw[1]  * r0.y + c_kw[2]  * r0.z + c_kw[3]  * r0.w;
    acc += c_kw[4]  * r1.x + c_kw[5]  * r1.y + c_kw[6]  * r1.z + c_kw[7]  * r1.w;
    acc += c_kw[8]  * r2.x + c_kw[9]  * r2.y + c_kw[10] * r2.z + c_kw[11] * r2.w;
    acc += c_kw[12] * r3.x + c_kw[13] * r3.y + c_kw[14] * r3.z + c_kw[15] * r3.w;

    __stcs(out + o, acc);
}

extern "C" void kernel_launch(void* const* d_in, const int* in_sizes, int n_in,
                              void* d_out, int out_size)
{
    const float* x    = (const float*)d_in[0];   // (16,8,1024,1024) fp32
    const float* kern = (const float*)d_in[1];   // (4,4) fp32
    float* out = (float*)d_out;                  // (16,8,256,256) fp32

    // Stage the 16 weights into constant memory: async device-to-device copy,
    // graph-capturable, deterministic (same source every call).
    cudaMemcpyToSymbolAsync(c_kw, kern, 16 * sizeof(float), 0,
                            cudaMemcpyDeviceToDevice);

    int total = N_ * C_ * HO_ * WO_;             // 16,777,216
    int threads = 256;
    int blocks = (total + threads - 1) / threads; // 65536
    Downsampler_24421184045082_kernel<<<blocks, threads>>>(x, out, total);
}

// round 16
// speedup vs baseline: 1.0072x; 1.0072x over previous
#include <cuda_runtime.h>
#include <cuda_bf16.h>

// Downsampler: (16,8,1024,1024) fp32, 4x4 Gaussian kernel, stride 4, VALID.
// Output (16,8,256,256) fp32. Non-overlapping windows -> pure streaming.
// R16 (= R11 retry #5, unchanged): exactly R7 (best total 83.2us; kernel
// 81.1us, 6.91 TB/s) with one micro change: block 256 -> 512 (halves CTA
// count; same occupancy/regs). Kernel is at the LTS/HBM compulsory-traffic
// ceiling; this is a launch-overhead tuner only.

#define N_  16
#define C_  8
#define H_  1024
#define W_  1024
#define F_  4
#define HO_ (H_ / F_)   // 256
#define WO_ (W_ / F_)   // 256

__global__ __launch_bounds__(512) void Downsampler_24421184045082_kernel(
    const float* __restrict__ x,
    const float* __restrict__ kern,
    float* __restrict__ out,
    int total)
{
    int o = blockIdx.x * blockDim.x + threadIdx.x;
    if (o >= total) return;

    // Decompose output index: o = ((nc * HO) + oh) * WO + ow
    int ow = o & (WO_ - 1);            // 256 = 2^8
    int oh = (o >> 8) & (HO_ - 1);
    int nc = o >> 16;

    // Weights: broadcast L1 hits after first warp; proven non-binding (R10).
    float k00 = __ldg(kern + 0),  k01 = __ldg(kern + 1),  k02 = __ldg(kern + 2),  k03 = __ldg(kern + 3);
    float k10 = __ldg(kern + 4),  k11 = __ldg(kern + 5),  k12 = __ldg(kern + 6),  k13 = __ldg(kern + 7);
    float k20 = __ldg(kern + 8),  k21 = __ldg(kern + 9),  k22 = __ldg(kern + 10), k23 = __ldg(kern + 11);
    float k30 = __ldg(kern + 12), k31 = __ldg(kern + 13), k32 = __ldg(kern + 14), k33 = __ldg(kern + 15);

    // Base of this thread's 4x4 patch, viewed as float4 rows.
    const float4* x4 = reinterpret_cast<const float4*>(x)
                     + (size_t)nc * (H_ * (W_ / 4))
                     + (size_t)(oh * F_) * (W_ / 4)
                     + ow;

    // 4 independent row loads, evict-first streaming policy (single-use data).
    float4 r0 = __ldcs(x4 + 0 * (W_ / 4));
    float4 r1 = __ldcs(x4 + 1 * (W_ / 4));
    float4 r2 = __ldcs(x4 + 2 * (W_ / 4));
    float4 r3 = __ldcs(x4 + 3 * (W_ / 4));

    float acc;
    acc  = k00 * r0.x + k01 * r0.y + k02 * r0.z + k03 * r0.w;
    acc += k10 * r1.x + k11 * r1.y + k12 * r1.z + k13 * r1.w;
    acc += k20 * r2.x + k21 * r2.y + k22 * r2.z + k23 * r2.w;
    acc += k30 * r3.x + k31 * r3.y + k32 * r3.z + k33 * r3.w;

    __stcs(out + o, acc);
}

extern "C" void kernel_launch(void* const* d_in, const int* in_sizes, int n_in,
                              void* d_out, int out_size)
{
    const float* x    = (const float*)d_in[0];   // (16,8,1024,1024) fp32
    const float* kern = (const float*)d_in[1];   // (4,4) fp32
    float* out = (float*)d_out;                  // (16,8,256,256) fp32

    int total = N_ * C_ * HO_ * WO_;             // 16,777,216
    int threads = 512;
    int blocks = (total + threads - 1) / threads; // 32768
    Downsampler_24421184045082_kernel<<<blocks, threads>>>(x, kern, out, total);
}